// round 2
// baseline (speedup 1.0000x reference)
#include <cuda_runtime.h>
#include <stdint.h>

// ---------------- problem constants ----------------
#define KDIM 30000
#define MDIM 3200            // B*L
#define NDIM 1000            // Co
#define NPAD 1024
#define BDIM 32
#define CDIM 104
#define NPOOL 10

// ---------------- GEMM tiling ----------------
#define MT 128
#define NT 128
#define KB 32
#define KSPLIT 2
#define KLEN (KDIM / KSPLIT)              // 15000
#define ITERS ((KLEN + KB - 1) / KB)      // 469 (tail 24)
#define STAGES 3
#define RSTRIDE 36                        // padded row stride in floats (bank-conflict-free)
#define STAGE_FLOATS ((MT + NT) * RSTRIDE)    // 9216
#define STAGE_BYTES (STAGE_FLOATS * 4)        // 36864
#define SMEM_BYTES (STAGES * STAGE_BYTES)     // 110592

// ---------------- static scratch ----------------
__device__ float g_xc[(size_t)MDIM * KDIM];        // tf32-rounded x
__device__ float g_wc[(size_t)NDIM * KDIM];        // tf32-rounded conv_w
__device__ float g_part[KSPLIT][(size_t)MDIM * NPAD];  // K-split partial sums
__device__ float g_pool[BDIM * NDIM * NPOOL];
__device__ float g_norm[BDIM];

// ---------------- helpers ----------------
static __device__ __forceinline__ uint32_t smem_u32(const void* p) {
    uint32_t a;
    asm("{ .reg .u64 t; cvta.to.shared.u64 t, %1; cvt.u32.u64 %0, t; }" : "=r"(a) : "l"(p));
    return a;
}
static __device__ __forceinline__ void cp_async16(uint32_t saddr, const float* gptr, uint32_t sz) {
    asm volatile("cp.async.cg.shared.global [%0], [%1], 16, %2;"
                 :: "r"(saddr), "l"(gptr), "r"(sz) : "memory");
}
static __device__ __forceinline__ void cp_commit() {
    asm volatile("cp.async.commit_group;" ::: "memory");
}
static __device__ __forceinline__ void cp_wait1() {
    asm volatile("cp.async.wait_group 1;" ::: "memory");
}
static __device__ __forceinline__ float cvt_rna_tf32(float f) {
    uint32_t u;
    asm("cvt.rna.tf32.f32 %0, %1;" : "=r"(u) : "f"(f));
    return __uint_as_float(u);
}

#define MMA_TF32(d, a, b)                                                          \
    asm volatile(                                                                  \
        "mma.sync.aligned.m16n8k8.row.col.f32.tf32.tf32.f32 "                      \
        "{%0,%1,%2,%3}, {%4,%5,%6,%7}, {%8,%9}, {%0,%1,%2,%3};"                    \
        : "+f"((d)[0]), "+f"((d)[1]), "+f"((d)[2]), "+f"((d)[3])                   \
        : "r"((a)[0]), "r"((a)[1]), "r"((a)[2]), "r"((a)[3]),                      \
          "r"((b)[0]), "r"((b)[1]))

// =====================================================================
// Kernel 0: round fp32 -> tf32-canonical fp32 (rna)
// =====================================================================
__global__ void __launch_bounds__(256) convert_kernel(const float* __restrict__ src,
                                                      float* __restrict__ dst, int n4) {
    int i = blockIdx.x * blockDim.x + threadIdx.x;
    int stride = gridDim.x * blockDim.x;
    for (; i < n4; i += stride) {
        float4 v = ((const float4*)src)[i];
        v.x = cvt_rna_tf32(v.x);
        v.y = cvt_rna_tf32(v.y);
        v.z = cvt_rna_tf32(v.z);
        v.w = cvt_rna_tf32(v.w);
        ((float4*)dst)[i] = v;
    }
}

// =====================================================================
// Kernel 1: GEMM partial[z][m][n] = sum_{k in split z} x[m,k]*w[n,k]
// CTA 128x128, 4 warps of 64x64, tf32 mma.sync, 3-stage cp.async.
// grid (25, 8, 2), block 128.
// =====================================================================
__global__ void __launch_bounds__(128, 2)
gemm_kernel() {
    extern __shared__ float sm[];
    const int tid = threadIdx.x;
    const int wid = tid >> 5;
    const int lane = tid & 31;
    const int g = lane >> 2;        // groupID
    const int tig = lane & 3;       // thread in group
    const int wm = wid >> 1;        // 0..1
    const int wn = wid & 1;         // 0..1
    const int m0 = blockIdx.x * MT;
    const int n0 = blockIdx.y * NT;
    const int z = blockIdx.z;
    const uint32_t sbase = smem_u32(sm);

    // ---- per-thread cp.async item setup (16 items: 256 rows x 8 slots) ----
    const float* gp[16];
    uint32_t soff[16];
    int slot4[16];
    uint32_t rowok[16];
    #pragma unroll
    for (int u = 0; u < 16; ++u) {
        int i = tid + u * 128;
        int row = i >> 3;
        int slot = i & 7;
        const float* base;
        uint32_t ok = 1;
        if (row < MT) {
            base = g_xc + (size_t)(m0 + row) * KDIM;
        } else {
            int n = n0 + row - MT;
            if (n >= NDIM) { n = NDIM - 1; ok = 0; }
            base = g_wc + (size_t)n * KDIM;
        }
        gp[u] = base + (size_t)z * KLEN + slot * 4;
        soff[u] = (uint32_t)(row * RSTRIDE + slot * 4) * 4u;
        slot4[u] = slot * 4;
        rowok[u] = ok;
    }

    #define ISSUE(it)                                                              \
        do {                                                                       \
            const int kb = (it) * KB;                                              \
            const int kleft = KLEN - kb;                                           \
            const uint32_t stb = sbase + ((it) % STAGES) * STAGE_BYTES;            \
            _Pragma("unroll")                                                      \
            for (int u = 0; u < 16; ++u) {                                         \
                uint32_t sz = (rowok[u] && slot4[u] < kleft) ? 16u : 0u;           \
                cp_async16(stb + soff[u], gp[u] + kb, sz);                         \
            }                                                                      \
        } while (0)

    // ---- prologue ----
    ISSUE(0); cp_commit();
    ISSUE(1); cp_commit();

    // ---- accumulators ----
    float acc[4][8][4];
    #pragma unroll
    for (int mt = 0; mt < 4; ++mt)
        #pragma unroll
        for (int nt = 0; nt < 8; ++nt)
            #pragma unroll
            for (int r = 0; r < 4; ++r) acc[mt][nt][r] = 0.f;

    const int a_row0 = wm * 64 + g;          // thread's A base row
    const int b_row0 = wn * 64 + g;          // thread's B base row (n index)

    // ---- main loop ----
    for (int it = 0; it < ITERS; ++it) {
        cp_wait1();
        __syncthreads();
        if (it + 2 < ITERS) { ISSUE(it + 2); }
        cp_commit();

        const float* As = sm + (it % STAGES) * STAGE_FLOATS;
        const float* Bs = As + MT * RSTRIDE;

        #pragma unroll
        for (int ks = 0; ks < 4; ++ks) {
            const int kc = ks * 8 + tig;
            uint32_t af[4][4];
            #pragma unroll
            for (int mt = 0; mt < 4; ++mt) {
                const int b0 = (a_row0 + mt * 16) * RSTRIDE + kc;
                af[mt][0] = __float_as_uint(As[b0]);
                af[mt][1] = __float_as_uint(As[b0 + 8 * RSTRIDE]);
                af[mt][2] = __float_as_uint(As[b0 + 4]);
                af[mt][3] = __float_as_uint(As[b0 + 8 * RSTRIDE + 4]);
            }
            uint32_t bf[8][2];
            #pragma unroll
            for (int nt = 0; nt < 8; ++nt) {
                const int b0 = (b_row0 + nt * 8) * RSTRIDE + kc;
                bf[nt][0] = __float_as_uint(Bs[b0]);
                bf[nt][1] = __float_as_uint(Bs[b0 + 4]);
            }
            #pragma unroll
            for (int mt = 0; mt < 4; ++mt)
                #pragma unroll
                for (int nt = 0; nt < 8; ++nt)
                    MMA_TF32(acc[mt][nt], af[mt], bf[nt]);
        }
    }

    // ---- epilogue: store partials (padded N, no predication needed) ----
    float* dst = &g_part[z][0];
    #pragma unroll
    for (int mt = 0; mt < 4; ++mt) {
        const int r0 = m0 + wm * 64 + mt * 16 + g;
        #pragma unroll
        for (int nt = 0; nt < 8; ++nt) {
            const int c = n0 + wn * 64 + nt * 8 + 2 * tig;
            *(float2*)&dst[(size_t)r0 * NPAD + c] =
                make_float2(acc[mt][nt][0], acc[mt][nt][1]);
            *(float2*)&dst[(size_t)(r0 + 8) * NPAD + c] =
                make_float2(acc[mt][nt][2], acc[mt][nt][3]);
        }
    }
    #undef ISSUE
}

// =====================================================================
// Kernel 2: bias + relu + avg-pool(10) + norm factor per batch
// grid 32, block 256 (250 active lanes of 4 channels each)
// =====================================================================
__global__ void __launch_bounds__(256) pool_norm_kernel(const float* __restrict__ conv_b) {
    const int b = blockIdx.x;
    const int tid = threadIdx.x;
    __shared__ float red[256];

    float ss = 0.f;
    if (tid < 250) {
        const int o4 = tid * 4;
        float4 bias = *(const float4*)(conv_b + o4);
        float4 acc[NPOOL];
        #pragma unroll
        for (int p = 0; p < NPOOL; ++p) acc[p] = make_float4(0.f, 0.f, 0.f, 0.f);

        #pragma unroll 2
        for (int p = 0; p < NPOOL; ++p) {
            #pragma unroll
            for (int i = 0; i < 10; ++i) {
                const size_t m = (size_t)(b * 100 + p * 10 + i) * NPAD + o4;
                float4 v0 = *(const float4*)&g_part[0][m];
                float4 v1 = *(const float4*)&g_part[1][m];
                acc[p].x += fmaxf(v0.x + v1.x + bias.x, 0.f);
                acc[p].y += fmaxf(v0.y + v1.y + bias.y, 0.f);
                acc[p].z += fmaxf(v0.z + v1.z + bias.z, 0.f);
                acc[p].w += fmaxf(v0.w + v1.w + bias.w, 0.f);
            }
        }
        float* pb = g_pool + (size_t)b * (NDIM * NPOOL);
        #pragma unroll
        for (int p = 0; p < NPOOL; ++p) {
            float4 v = acc[p];
            v.x *= 0.1f; v.y *= 0.1f; v.z *= 0.1f; v.w *= 0.1f;
            pb[(o4 + 0) * NPOOL + p] = v.x;
            pb[(o4 + 1) * NPOOL + p] = v.y;
            pb[(o4 + 2) * NPOOL + p] = v.z;
            pb[(o4 + 3) * NPOOL + p] = v.w;
            ss += v.x * v.x + v.y * v.y + v.z * v.z + v.w * v.w;
        }
    }
    red[tid] = ss;
    __syncthreads();
    for (int st = 128; st > 0; st >>= 1) {
        if (tid < st) red[tid] += red[tid + st];
        __syncthreads();
    }
    if (tid == 0) g_norm[b] = 1.0f / sqrtf(1.0f + red[0]);
}

// =====================================================================
// Kernel 3: logits
// =====================================================================
__global__ void __launch_bounds__(256) fc_kernel(const float* __restrict__ fc_w,
                                                 const float* __restrict__ fc_b,
                                                 float* __restrict__ out) {
    const int c = blockIdx.x;
    const int wid = threadIdx.x >> 5;
    const int lane = threadIdx.x & 31;
    const float4* wrow = (const float4*)(fc_w + (size_t)c * (NDIM * NPOOL));

    for (int b = wid; b < BDIM; b += 8) {
        const float4* pr = (const float4*)(g_pool + (size_t)b * (NDIM * NPOOL));
        float acc = 0.f;
        for (int k = lane; k < (NDIM * NPOOL) / 4; k += 32) {
            float4 w4 = wrow[k];
            float4 p4 = pr[k];
            acc += w4.x * p4.x + w4.y * p4.y + w4.z * p4.z + w4.w * p4.w;
        }
        #pragma unroll
        for (int off = 16; off > 0; off >>= 1)
            acc += __shfl_xor_sync(0xFFFFFFFFu, acc, off);
        if (lane == 0) out[b * CDIM + c] = fc_b[c] + g_norm[b] * acc;
    }
}

// =====================================================================
extern "C" void kernel_launch(void* const* d_in, const int* in_sizes, int n_in,
                              void* d_out, int out_size) {
    const float* x      = (const float*)d_in[0];  // [32,100,30000]
    const float* conv_w = (const float*)d_in[1];  // [1000,30000]
    const float* conv_b = (const float*)d_in[2];  // [1000]
    const float* fc_w   = (const float*)d_in[3];  // [104,10000]
    const float* fc_b   = (const float*)d_in[4];  // [104]
    float* out = (float*)d_out;                   // [32,104]

    static int configured = 0;
    if (!configured) {
        cudaFuncSetAttribute(gemm_kernel,
                             cudaFuncAttributeMaxDynamicSharedMemorySize, SMEM_BYTES);
        configured = 1;
    }

    float* xc; cudaGetSymbolAddress((void**)&xc, g_xc);
    float* wc; cudaGetSymbolAddress((void**)&wc, g_wc);

    convert_kernel<<<2048, 256>>>(x, xc, (MDIM * KDIM) / 4);
    convert_kernel<<<1024, 256>>>(conv_w, wc, (NDIM * KDIM) / 4);
    gemm_kernel<<<dim3(MDIM / MT, 8, KSPLIT), 128, SMEM_BYTES>>>();
    pool_norm_kernel<<<BDIM, 256>>>(conv_b);
    fc_kernel<<<CDIM, 256>>>(fc_w, fc_b, out);
}